// round 1
// baseline (speedup 1.0000x reference)
#include <cuda_runtime.h>
#include <math.h>

#define BATCH 32
#define TX 1024
#define EDIM 1024
#define DDIM 1024
#define ADIM 1024
#define NEG_INF -1000000000.0f

#define BM 128
#define BN 128
#define BK 16

// scratch: dec_proj (B x A)
__device__ float g_dec_proj[BATCH * ADIM];

__device__ __forceinline__ float fast_tanh(float x) {
    x = fminf(fmaxf(x, -15.0f), 15.0f);
    float e = __expf(2.0f * x);
    return __fdividef(e - 1.0f, e + 1.0f);
}

// dec_proj[b][a] = sum_d dec_hidden[b][d] * W_w[a][d]   (one warp per output)
__global__ void dec_proj_kernel(const float* __restrict__ dec_hidden,
                                const float* __restrict__ W_w) {
    int gwarp = (blockIdx.x * blockDim.x + threadIdx.x) >> 5;
    int lane = threadIdx.x & 31;
    int b = gwarp >> 10;          // / ADIM
    int a = gwarp & 1023;         // % ADIM
    const float* dh = dec_hidden + (size_t)b * DDIM;
    const float* w  = W_w + (size_t)a * (DDIM + EDIM);   // W_dec = W_w[:, :D]
    float s = 0.0f;
    #pragma unroll 4
    for (int d = lane; d < DDIM; d += 32) s += dh[d] * w[d];
    #pragma unroll
    for (int o = 16; o > 0; o >>= 1) s += __shfl_down_sync(0xffffffffu, s, o);
    if (lane == 0) g_dec_proj[gwarp] = s;
}

// Fused: enc_proj tile GEMM + tanh epilogue + dot with v -> accumulate scores.
// grid = (ADIM/BN = 8, (BATCH*TX)/BM = 256); block = 256 threads (16x16, 8x8 micro)
__global__ __launch_bounds__(256, 2)
void fused_scores_kernel(const float* __restrict__ enc,   // (B*TX, E)
                         const float* __restrict__ W_w,   // (A, D+E)
                         const float* __restrict__ W_b,   // (A,)
                         const float* __restrict__ v_w,   // (A,)
                         float* __restrict__ scores)      // (B*TX,) pre-zeroed
{
    __shared__ float As[BK][BM];
    __shared__ float Bs[BK][BN];
    __shared__ float s_score[BM];

    const int tid = threadIdx.x;
    const int tx = tid & 15;
    const int ty = tid >> 4;
    const int n0 = blockIdx.x * BN;
    const int r0 = blockIdx.y * BM;
    const int bb = r0 >> 10;           // batch index (BM divides TX)

    float acc[8][8];
    #pragma unroll
    for (int i = 0; i < 8; i++)
        #pragma unroll
        for (int j = 0; j < 8; j++) acc[i][j] = 0.0f;

    const float* Xbase = enc + (size_t)r0 * EDIM;

    for (int k0 = 0; k0 < EDIM; k0 += BK) {
        // load X tile (BM x BK) transposed into As[k][m]
        #pragma unroll
        for (int l = 0; l < 2; l++) {
            int s = tid + l * 256;           // 512 float4 slots
            int m = s >> 2, kq = s & 3;
            float4 x = *(const float4*)(Xbase + (size_t)m * EDIM + k0 + kq * 4);
            As[kq * 4 + 0][m] = x.x;
            As[kq * 4 + 1][m] = x.y;
            As[kq * 4 + 2][m] = x.z;
            As[kq * 4 + 3][m] = x.w;
        }
        // load W_enc tile (BN x BK) transposed into Bs[k][c]
        #pragma unroll
        for (int l = 0; l < 2; l++) {
            int s = tid + l * 256;
            int c = s >> 2, kq = s & 3;
            float4 w = *(const float4*)(W_w + (size_t)(n0 + c) * (DDIM + EDIM)
                                        + DDIM + k0 + kq * 4);
            Bs[kq * 4 + 0][c] = w.x;
            Bs[kq * 4 + 1][c] = w.y;
            Bs[kq * 4 + 2][c] = w.z;
            Bs[kq * 4 + 3][c] = w.w;
        }
        __syncthreads();

        #pragma unroll
        for (int kk = 0; kk < BK; kk++) {
            float4 t0 = *(const float4*)&As[kk][ty * 8];
            float4 t1 = *(const float4*)&As[kk][ty * 8 + 4];
            float4 u0 = *(const float4*)&Bs[kk][tx * 8];
            float4 u1 = *(const float4*)&Bs[kk][tx * 8 + 4];
            float af[8] = {t0.x, t0.y, t0.z, t0.w, t1.x, t1.y, t1.z, t1.w};
            float bf[8] = {u0.x, u0.y, u0.z, u0.w, u1.x, u1.y, u1.z, u1.w};
            #pragma unroll
            for (int i = 0; i < 8; i++)
                #pragma unroll
                for (int j = 0; j < 8; j++) acc[i][j] += af[i] * bf[j];
        }
        __syncthreads();
    }

    // epilogue: partial score over this A-tile
    if (tid < BM) s_score[tid] = 0.0f;
    __syncthreads();

    float vv[8], dp[8];
    #pragma unroll
    for (int j = 0; j < 8; j++) {
        int cg = n0 + tx * 8 + j;
        vv[j] = v_w[cg];
        dp[j] = g_dec_proj[bb * ADIM + cg] + W_b[cg];
    }
    #pragma unroll
    for (int i = 0; i < 8; i++) {
        float p = 0.0f;
        #pragma unroll
        for (int j = 0; j < 8; j++)
            p += fast_tanh(acc[i][j] + dp[j]) * vv[j];
        atomicAdd(&s_score[ty * 8 + i], p);
    }
    __syncthreads();
    if (tid < BM) atomicAdd(&scores[r0 + tid], s_score[tid]);
}

// masked softmax over Tx for each b; in-place on alpha region
__global__ void softmax_kernel(const int* __restrict__ mask,
                               float* __restrict__ alpha) {
    const int b = blockIdx.x;
    const int tid = threadIdx.x;     // 256 threads, 4 elems each
    __shared__ float red[8];

    float vals[4];
    float mx = -3.0e38f;
    #pragma unroll
    for (int i = 0; i < 4; i++) {
        int t = tid + i * 256;
        float s = alpha[b * TX + t];
        if (mask[b * TX + t] == 0) s = NEG_INF;
        vals[i] = s;
        mx = fmaxf(mx, s);
    }
    #pragma unroll
    for (int o = 16; o > 0; o >>= 1) mx = fmaxf(mx, __shfl_xor_sync(0xffffffffu, mx, o));
    if ((tid & 31) == 0) red[tid >> 5] = mx;
    __syncthreads();
    float bmx = red[0];
    #pragma unroll
    for (int w = 1; w < 8; w++) bmx = fmaxf(bmx, red[w]);

    float sum = 0.0f;
    #pragma unroll
    for (int i = 0; i < 4; i++) {
        vals[i] = __expf(vals[i] - bmx);
        sum += vals[i];
    }
    #pragma unroll
    for (int o = 16; o > 0; o >>= 1) sum += __shfl_xor_sync(0xffffffffu, sum, o);
    __syncthreads();
    if ((tid & 31) == 0) red[tid >> 5] = sum;
    __syncthreads();
    float bsum = 0.0f;
    #pragma unroll
    for (int w = 0; w < 8; w++) bsum += red[w];

    float inv = __fdividef(1.0f, bsum);
    #pragma unroll
    for (int i = 0; i < 4; i++)
        alpha[b * TX + tid + i * 256] = vals[i] * inv;
}

// context[b][e] = sum_t alpha[b][t] * enc[b][t][e]; grid (B, 16), chunks of 64 t
__global__ void context_kernel(const float* __restrict__ enc,
                               const float* __restrict__ alpha,
                               float* __restrict__ context) {   // pre-zeroed
    const int b = blockIdx.x;
    const int chunk = blockIdx.y;
    const int tid = threadIdx.x;     // 256: float4 over E
    const float4* ebase = (const float4*)(enc + ((size_t)b * TX + chunk * 64) * EDIM);
    const float* al = alpha + b * TX + chunk * 64;
    float4 acc = make_float4(0.f, 0.f, 0.f, 0.f);
    #pragma unroll 4
    for (int t = 0; t < 64; t++) {
        float a = al[t];
        float4 x = ebase[(size_t)t * 256 + tid];
        acc.x += a * x.x;
        acc.y += a * x.y;
        acc.z += a * x.z;
        acc.w += a * x.w;
    }
    float* c = context + (size_t)b * EDIM + tid * 4;
    atomicAdd(c + 0, acc.x);
    atomicAdd(c + 1, acc.y);
    atomicAdd(c + 2, acc.z);
    atomicAdd(c + 3, acc.w);
}

extern "C" void kernel_launch(void* const* d_in, const int* in_sizes, int n_in,
                              void* d_out, int out_size) {
    const float* dec_hidden = (const float*)d_in[0];   // (32,1024)
    const float* enc        = (const float*)d_in[1];   // (32,1024,1024)
    const int*   mask       = (const int*)d_in[2];     // (32,1024)
    const float* W_w        = (const float*)d_in[3];   // (1024,2048)
    const float* W_b        = (const float*)d_in[4];   // (1024,)
    const float* v_w        = (const float*)d_in[5];   // (1,1024)

    float* context = (float*)d_out;                    // first 32*1024
    float* alpha   = (float*)d_out + BATCH * TX;       // next 32*1024 (scores scratch)

    // zero both output halves (scores + context accumulate via atomics)
    cudaMemsetAsync(d_out, 0, (size_t)(BATCH * EDIM + BATCH * TX) * sizeof(float), 0);

    // dec_proj: 32768 warp-outputs, 8 warps/block
    dec_proj_kernel<<<(BATCH * ADIM) / 8, 256>>>(dec_hidden, W_w);

    // fused GEMM + tanh + v-dot -> scores (in alpha region)
    dim3 grid(ADIM / BN, (BATCH * TX) / BM);
    fused_scores_kernel<<<grid, 256>>>(enc, W_w, W_b, v_w, alpha);

    // masked softmax in place
    softmax_kernel<<<BATCH, 256>>>(mask, alpha);

    // context
    dim3 cgrid(BATCH, 16);
    context_kernel<<<cgrid, 256>>>(enc, alpha, context);
}

// round 5
// speedup vs baseline: 2.4075x; 2.4075x over previous
#include <cuda_runtime.h>
#include <cuda_bf16.h>
#include <cstdint>
#include <math.h>

#define BATCH 32
#define TX 1024
#define EDIM 1024
#define DDIM 1024
#define ADIM 1024
#define NEG_INF -1000000000.0f

// ---- fused GEMM config ----
#define BM 128
#define BN 128
#define BK 32
#define K_TILES (EDIM / BK)      // 32

// smem tile offsets (single 32KB stage)
#define AHI 0
#define ALO 8192
#define BHI 16384
#define BLO 24576

// small sanctioned scratch (proved safe in round 1)
__device__ float g_dec_proj[BATCH * ADIM];

__device__ __forceinline__ uint32_t smem_u32(const void* p) {
    uint32_t a;
    asm("{ .reg .u64 t; cvta.to.shared.u64 t, %1; cvt.u32.u64 %0, t; }" : "=r"(a) : "l"(p));
    return a;
}

__device__ __forceinline__ void ldsm4(uint32_t& r0, uint32_t& r1, uint32_t& r2,
                                      uint32_t& r3, uint32_t addr) {
    asm volatile("ldmatrix.sync.aligned.m8n8.x4.shared.b16 {%0,%1,%2,%3}, [%4];"
                 : "=r"(r0), "=r"(r1), "=r"(r2), "=r"(r3) : "r"(addr));
}

__device__ __forceinline__ void mma16816(float* c, const uint32_t* a,
                                         uint32_t b0, uint32_t b1) {
    asm volatile(
        "mma.sync.aligned.m16n8k16.row.col.f32.bf16.bf16.f32 "
        "{%0,%1,%2,%3}, {%4,%5,%6,%7}, {%8,%9}, {%0,%1,%2,%3};"
        : "+f"(c[0]), "+f"(c[1]), "+f"(c[2]), "+f"(c[3])
        : "r"(a[0]), "r"(a[1]), "r"(a[2]), "r"(a[3]), "r"(b0), "r"(b1));
}

// MUFU-free tanh, ~1e-6 abs error
__device__ __forceinline__ float tanh_fast(float x) {
    float ax = fminf(fabsf(x), 10.0f);
    float y = -2.88539008f * ax;                    // -2*log2(e)*|x|
    int i = __float2int_rn(y);
    float f = y - (float)i;                         // [-0.5, 0.5]
    float p = 1.33335581e-3f;
    p = fmaf(p, f, 9.61812911e-3f);
    p = fmaf(p, f, 5.55041087e-2f);
    p = fmaf(p, f, 2.40226507e-1f);
    p = fmaf(p, f, 6.93147180e-1f);
    p = fmaf(p, f, 1.0f);
    float z = p * __int_as_float((i + 127) << 23);  // e^{-2|x|} in (0,1]
    float d = 1.0f + z;
    float r = __int_as_float(0x7EF311C3u - __float_as_int(d));
    r = r * (2.0f - d * r);
    r = r * (2.0f - d * r);
    r = r * (2.0f - d * r);
    float t = (1.0f - z) * r;
    return copysignf(t, x);
}

// 8 fp32 -> 8 bf16 hi (uint4) + 8 bf16 lo (uint4)
__device__ __forceinline__ void split8(float4 a, float4 b, uint4& H, uint4& L) {
    union { __nv_bfloat162 b2; uint32_t u; } h0, h1, h2, h3, l0, l1, l2, l3;
    h0.b2 = __floats2bfloat162_rn(a.x, a.y);
    h1.b2 = __floats2bfloat162_rn(a.z, a.w);
    h2.b2 = __floats2bfloat162_rn(b.x, b.y);
    h3.b2 = __floats2bfloat162_rn(b.z, b.w);
    float2 f0 = __bfloat1622float2(h0.b2);
    float2 f1 = __bfloat1622float2(h1.b2);
    float2 f2 = __bfloat1622float2(h2.b2);
    float2 f3 = __bfloat1622float2(h3.b2);
    l0.b2 = __floats2bfloat162_rn(a.x - f0.x, a.y - f0.y);
    l1.b2 = __floats2bfloat162_rn(a.z - f1.x, a.w - f1.y);
    l2.b2 = __floats2bfloat162_rn(b.x - f2.x, b.y - f2.y);
    l3.b2 = __floats2bfloat162_rn(b.z - f3.x, b.w - f3.y);
    H = make_uint4(h0.u, h1.u, h2.u, h3.u);
    L = make_uint4(l0.u, l1.u, l2.u, l3.u);
}

// ---- dec_proj (warp per output) ----
__global__ void dec_proj_kernel(const float* __restrict__ dec_hidden,
                                const float* __restrict__ W_w) {
    int gwarp = (blockIdx.x * blockDim.x + threadIdx.x) >> 5;
    int lane = threadIdx.x & 31;
    int b = gwarp >> 10;
    int a = gwarp & 1023;
    const float* dh = dec_hidden + (size_t)b * DDIM;
    const float* w  = W_w + (size_t)a * (DDIM + EDIM);
    float s = 0.0f;
    #pragma unroll 4
    for (int d = lane; d < DDIM; d += 32) s += dh[d] * w[d];
    #pragma unroll
    for (int o = 16; o > 0; o >>= 1) s += __shfl_down_sync(0xffffffffu, s, o);
    if (lane == 0) g_dec_proj[gwarp] = s;
}

// ---- fused HMMA scores kernel ----
// grid (8 n-chunks, 256 row-blocks), 256 threads (8 warps: 4m x 2n), tile 128x128
__global__ __launch_bounds__(256)
void fused_scores_hmma(const float* __restrict__ enc,
                       const float* __restrict__ W_w,
                       const float* __restrict__ W_b,
                       const float* __restrict__ v_w,
                       float* __restrict__ scores) {
    __shared__ __align__(128) char tile[32768];
    __shared__ float dpb_s[BM];
    __shared__ float vw_s[BM];
    __shared__ float s_score[BM];

    const int tid = threadIdx.x;
    const int lane = tid & 31;
    const int wid = tid >> 5;
    const int wm = wid >> 1;          // 0..3
    const int wn = wid & 1;           // 0..1
    const int n0 = blockIdx.x * BN;
    const int r0 = blockIdx.y * BM;
    const int bb = r0 >> 10;

    const uint32_t sb = smem_u32(tile);

    if (tid < BM) {
        dpb_s[tid]   = g_dec_proj[bb * ADIM + n0 + tid] + W_b[n0 + tid];
        vw_s[tid]    = v_w[n0 + tid];
        s_score[tid] = 0.0f;
    }

    float acc[2][8][4];
    #pragma unroll
    for (int mi = 0; mi < 2; mi++)
        #pragma unroll
        for (int nj = 0; nj < 8; nj++)
            #pragma unroll
            for (int q = 0; q < 4; q++) acc[mi][nj][q] = 0.0f;

    // per-thread tile slot (2 slots each of A and B): 8 fp32 per slot
    const int cid0 = tid * 2;
    const int row0 = cid0 >> 2, seg0 = cid0 & 3;
    const int row1 = (cid0 + 1) >> 2, seg1 = (cid0 + 1) & 3;
    const uint32_t off0 = (uint32_t)row0 * 64 + (((uint32_t)seg0 * 16) ^ (((uint32_t)row0 & 6) << 3));
    const uint32_t off1 = (uint32_t)row1 * 64 + (((uint32_t)seg1 * 16) ^ (((uint32_t)row1 & 6) << 3));

    const float* gA0 = enc + (size_t)(r0 + row0) * EDIM + seg0 * 8;
    const float* gA1 = enc + (size_t)(r0 + row1) * EDIM + seg1 * 8;
    const float* gB0 = W_w + (size_t)(n0 + row0) * (DDIM + EDIM) + DDIM + seg0 * 8;
    const float* gB1 = W_w + (size_t)(n0 + row1) * (DDIM + EDIM) + DDIM + seg1 * 8;

    // per-lane ldmatrix offsets (same geometry as the store swizzle)
    const uint32_t axor  = (lane & 6) << 3;
    const uint32_t a_row = (uint32_t)(wm * 32 + (lane & 15)) * 64;
    const uint32_t a_kb  = (lane >> 4) << 4;
    const uint32_t b_row = (uint32_t)((lane & 7) + ((lane >> 4) << 3)) * 64;
    const uint32_t b_kb  = ((lane >> 3) & 1) << 4;

    float4 ra[4], rb[4];
    // prefetch tile 0
    {
        ra[0] = *(const float4*)(gA0);     ra[1] = *(const float4*)(gA0 + 4);
        ra[2] = *(const float4*)(gA1);     ra[3] = *(const float4*)(gA1 + 4);
        rb[0] = *(const float4*)(gB0);     rb[1] = *(const float4*)(gB0 + 4);
        rb[2] = *(const float4*)(gB1);     rb[3] = *(const float4*)(gB1 + 4);
    }

    for (int kt = 0; kt < K_TILES; kt++) {
        if (kt) __syncthreads();                 // all MMAs of kt-1 done

        // split + store current tile
        {
            uint4 H, L;
            split8(ra[0], ra[1], H, L);
            *(uint4*)(tile + AHI + off0) = H;  *(uint4*)(tile + ALO + off0) = L;
            split8(ra[2], ra[3], H, L);
            *(uint4*)(tile + AHI + off1) = H;  *(uint4*)(tile + ALO + off1) = L;
            split8(rb[0], rb[1], H, L);
            *(uint4*)(tile + BHI + off0) = H;  *(uint4*)(tile + BLO + off0) = L;
            split8(rb[2], rb[3], H, L);
            *(uint4*)(tile + BHI + off1) = H;  *(uint4*)(tile + BLO + off1) = L;
        }
        // prefetch next tile (LDG latency hides under MMA phase)
        if (kt + 1 < K_TILES) {
            int k0 = (kt + 1) * BK;
            ra[0] = *(const float4*)(gA0 + k0);  ra[1] = *(const float4*)(gA0 + k0 + 4);
            ra[2] = *(const float4*)(gA1 + k0);  ra[3] = *(const float4*)(gA1 + k0 + 4);
            rb[0] = *(const float4*)(gB0 + k0);  rb[1] = *(const float4*)(gB0 + k0 + 4);
            rb[2] = *(const float4*)(gB1 + k0);  rb[3] = *(const float4*)(gB1 + k0 + 4);
        }
        __syncthreads();                         // stores visible

        #pragma unroll
        for (int s = 0; s < 2; s++) {
            uint32_t ah[2][4], alo[2][4];
            #pragma unroll
            for (int mi = 0; mi < 2; mi++) {
                uint32_t ao = a_row + (uint32_t)mi * 1024 + ((a_kb + s * 32) ^ axor);
                ldsm4(ah[mi][0], ah[mi][1], ah[mi][2], ah[mi][3], sb + AHI + ao);
                ldsm4(alo[mi][0], alo[mi][1], alo[mi][2], alo[mi][3], sb + ALO + ao);
            }
            uint32_t bh[4][4], blo[4][4];
            #pragma unroll
            for (int q = 0; q < 4; q++) {
                uint32_t bo = b_row + (uint32_t)(wn * 4 + q) * 1024 + ((b_kb + s * 32) ^ axor);
                ldsm4(bh[q][0], bh[q][1], bh[q][2], bh[q][3], sb + BHI + bo);
                ldsm4(blo[q][0], blo[q][1], blo[q][2], blo[q][3], sb + BLO + bo);
            }
            #pragma unroll
            for (int mi = 0; mi < 2; mi++)
                #pragma unroll
                for (int nj = 0; nj < 8; nj++) {
                    uint32_t b0h = bh[nj >> 1][(nj & 1) * 2];
                    uint32_t b1h = bh[nj >> 1][(nj & 1) * 2 + 1];
                    uint32_t b0l = blo[nj >> 1][(nj & 1) * 2];
                    uint32_t b1l = blo[nj >> 1][(nj & 1) * 2 + 1];
                    mma16816(acc[mi][nj], ah[mi], b0h, b1h);
                    mma16816(acc[mi][nj], ah[mi], b0l, b1l);
                    mma16816(acc[mi][nj], alo[mi], b0h, b1h);
                }
        }
    }

    // epilogue: tanh + v-dot, quad reduce, smem accumulate
    #pragma unroll
    for (int mi = 0; mi < 2; mi++) {
        float sa = 0.0f, sb_ = 0.0f;
        #pragma unroll
        for (int nj = 0; nj < 8; nj++) {
            int c0 = wn * 64 + nj * 8 + (lane & 3) * 2;
            float dp0 = dpb_s[c0], dp1 = dpb_s[c0 + 1];
            float v0 = vw_s[c0], v1 = vw_s[c0 + 1];
            sa  += tanh_fast(acc[mi][nj][0] + dp0) * v0
                 + tanh_fast(acc[mi][nj][1] + dp1) * v1;
            sb_ += tanh_fast(acc[mi][nj][2] + dp0) * v0
                 + tanh_fast(acc[mi][nj][3] + dp1) * v1;
        }
        sa  += __shfl_xor_sync(0xffffffffu, sa, 1);
        sa  += __shfl_xor_sync(0xffffffffu, sa, 2);
        sb_ += __shfl_xor_sync(0xffffffffu, sb_, 1);
        sb_ += __shfl_xor_sync(0xffffffffu, sb_, 2);
        if ((lane & 3) == 0) {
            int r = wm * 32 + mi * 16 + (lane >> 2);
            atomicAdd(&s_score[r], sa);
            atomicAdd(&s_score[r + 8], sb_);
        }
    }
    __syncthreads();
    if (tid < BM) atomicAdd(&scores[r0 + tid], s_score[tid]);
}

// ---- masked softmax ----
__global__ void softmax_kernel(const int* __restrict__ mask,
                               float* __restrict__ alpha) {
    const int b = blockIdx.x;
    const int tid = threadIdx.x;
    __shared__ float red[8];

    float vals[4];
    float mx = -3.0e38f;
    #pragma unroll
    for (int i = 0; i < 4; i++) {
        int t = tid + i * 256;
        float s = alpha[b * TX + t];
        if (mask[b * TX + t] == 0) s = NEG_INF;
        vals[i] = s;
        mx = fmaxf(mx, s);
    }
    #pragma unroll
    for (int o = 16; o > 0; o >>= 1) mx = fmaxf(mx, __shfl_xor_sync(0xffffffffu, mx, o));
    if ((tid & 31) == 0) red[tid >> 5] = mx;
    __syncthreads();
    float bmx = red[0];
    #pragma unroll
    for (int w = 1; w < 8; w++) bmx = fmaxf(bmx, red[w]);

    float sum = 0.0f;
    #pragma unroll
    for (int i = 0; i < 4; i++) {
        vals[i] = __expf(vals[i] - bmx);
        sum += vals[i];
    }
    #pragma unroll
    for (int o = 16; o > 0; o >>= 1) sum += __shfl_xor_sync(0xffffffffu, sum, o);
    __syncthreads();
    if ((tid & 31) == 0) red[tid >> 5] = sum;
    __syncthreads();
    float bsum = 0.0f;
    #pragma unroll
    for (int w = 0; w < 8; w++) bsum += red[w];

    float inv = __fdividef(1.0f, bsum);
    #pragma unroll
    for (int i = 0; i < 4; i++)
        alpha[b * TX + tid + i * 256] = vals[i] * inv;
}

// ---- context ----
__global__ void context_kernel(const float* __restrict__ enc,
                               const float* __restrict__ alpha,
                               float* __restrict__ context) {
    const int b = blockIdx.x;
    const int chunk = blockIdx.y;
    const int tid = threadIdx.x;
    const float4* ebase = (const float4*)(enc + ((size_t)b * TX + chunk * 64) * EDIM);
    const float* al = alpha + b * TX + chunk * 64;
    float4 acc = make_float4(0.f, 0.f, 0.f, 0.f);
    #pragma unroll 4
    for (int t = 0; t < 64; t++) {
        float a = al[t];
        float4 x = ebase[(size_t)t * 256 + tid];
        acc.x += a * x.x;
        acc.y += a * x.y;
        acc.z += a * x.z;
        acc.w += a * x.w;
    }
    float* c = context + (size_t)b * EDIM + tid * 4;
    atomicAdd(c + 0, acc.x);
    atomicAdd(c + 1, acc.y);
    atomicAdd(c + 2, acc.z);
    atomicAdd(c + 3, acc.w);
}

extern "C" void kernel_launch(void* const* d_in, const int* in_sizes, int n_in,
                              void* d_out, int out_size) {
    const float* dec_hidden = (const float*)d_in[0];
    const float* enc        = (const float*)d_in[1];
    const int*   mask       = (const int*)d_in[2];
    const float* W_w        = (const float*)d_in[3];
    const float* W_b        = (const float*)d_in[4];
    const float* v_w        = (const float*)d_in[5];

    float* context = (float*)d_out;
    float* alpha   = (float*)d_out + BATCH * TX;

    // zero context + scores (both accumulated via atomics)
    cudaMemsetAsync(d_out, 0, (size_t)(BATCH * EDIM + BATCH * TX) * sizeof(float), 0);

    dec_proj_kernel<<<(BATCH * ADIM) / 8, 256>>>(dec_hidden, W_w);

    dim3 grid(ADIM / BN, (BATCH * TX) / BM);
    fused_scores_hmma<<<grid, 256>>>(enc, W_w, W_b, v_w, alpha);

    softmax_kernel<<<BATCH, 256>>>(mask, alpha);

    dim3 cgrid(BATCH, 16);
    context_kernel<<<cgrid, 256>>>(enc, alpha, context);
}